// round 16
// baseline (speedup 1.0000x reference)
#include <cuda_runtime.h>
#include <cuda_fp16.h>
#include <cstdint>

#define NB 4
#define NQ 2048
#define NK 2048
#define ND 1024

// ---------------- device scratch (no runtime allocation allowed) ----------------
__device__ float g_e[NB * NK];                          // exp(rowsum(value)/32)
__device__ float g_w[(size_t)NB * NQ * NK];             // weights scratch (if not in d_out)
__device__ float g_ctx[(size_t)NB * NQ * ND];           // context scratch (if not in d_out)
__device__ __half g_wh[(size_t)NB * NQ * NK];           // fp16(1024*w) GEMM A operand
__device__ __half g_vh[(size_t)NB * NK * ND];           // fp16(value)  GEMM B operand

// ---------------- helpers ----------------
__device__ __forceinline__ uint32_t smem_u32(const void* p) {
    uint32_t a;
    asm("{ .reg .u64 t; cvta.to.shared.u64 t, %1; cvt.u32.u64 %0, t; }" : "=r"(a) : "l"(p));
    return a;
}

__device__ __forceinline__ void cp16(uint32_t s, const void* g) {
    asm volatile("cp.async.cg.shared.global [%0], [%1], 16;\n" :: "r"(s), "l"(g));
}

__device__ __forceinline__ uint32_t lds_u32(uint32_t a) {
    uint32_t v;
    asm volatile("ld.shared.b32 %0, [%1];" : "=r"(v) : "r"(a));
    return v;
}

// ldmatrix x4 (non-trans): 4 8-row x 16B matrices; lane l addresses matrix l>>3's
// row l&7. For f16 A m16n8k16: mat0=rows0-7/k0-7, mat1=rows8-15/k0-7,
// mat2=rows0-7/k8-15, mat3=rows8-15/k8-15 -> regs a0..a3 exactly.
__device__ __forceinline__ void ldsm4(uint32_t& r0, uint32_t& r1, uint32_t& r2,
                                      uint32_t& r3, uint32_t addr) {
    asm volatile("ldmatrix.sync.aligned.m8n8.x4.shared.b16 {%0,%1,%2,%3}, [%4];"
                 : "=r"(r0), "=r"(r1), "=r"(r2), "=r"(r3) : "r"(addr));
}

// ldmatrix x4 trans: B (k-major) -> b fragments.
__device__ __forceinline__ void ldsm4t(uint32_t& r0, uint32_t& r1, uint32_t& r2,
                                       uint32_t& r3, uint32_t addr) {
    asm volatile("ldmatrix.sync.aligned.m8n8.x4.trans.shared.b16 {%0,%1,%2,%3}, [%4];"
                 : "=r"(r0), "=r"(r1), "=r"(r2), "=r"(r3) : "r"(addr));
}

// ---------------- kernel 1: e + fp16 copy of value ----------------
// warp-per-row; vh written as 16B uint4 (pairs of float4).
__global__ void k_rowexp(const float* __restrict__ v) {
    int row = blockIdx.x * 8 + (threadIdx.x >> 5);
    int lane = threadIdx.x & 31;
    const float4* p = reinterpret_cast<const float4*>(v + (size_t)row * ND);
    uint4* vh = reinterpret_cast<uint4*>(g_vh + (size_t)row * ND);
    float s = 0.f;
#pragma unroll
    for (int i = 0; i < 4; i++) {
        float4 f0 = p[2 * lane + 64 * i];
        float4 f1 = p[2 * lane + 1 + 64 * i];
        s += (f0.x + f0.y) + (f0.z + f0.w) + (f1.x + f1.y) + (f1.z + f1.w);
        __half2 a = __floats2half2_rn(f0.x, f0.y);
        __half2 b = __floats2half2_rn(f0.z, f0.w);
        __half2 c = __floats2half2_rn(f1.x, f1.y);
        __half2 d = __floats2half2_rn(f1.z, f1.w);
        uint4 u;
        u.x = *reinterpret_cast<uint32_t*>(&a);
        u.y = *reinterpret_cast<uint32_t*>(&b);
        u.z = *reinterpret_cast<uint32_t*>(&c);
        u.w = *reinterpret_cast<uint32_t*>(&d);
        vh[lane + 32 * i] = u;
    }
#pragma unroll
    for (int o = 16; o; o >>= 1) s += __shfl_xor_sync(0xffffffffu, s, o);
    if (lane == 0) g_e[row] = expf(s * 0.03125f);  // / sqrt(1024)
}

// ---------------- kernel 2: wh = fp16(1024 * softmax-weights) ----------------
// w[b,q,k] = mask * e[b,k] / sum_k(mask * e[b,k])  (q_sum cancels in softmax).
// fp32 w output is written later by k_gemm (d0==0 CTAs) from this wh — saves
// the 64MB store here; weight precision becomes fp16 (~1.4e-4 rms, OK).
__global__ void k_weights(const int* __restrict__ mask) {
    int row = blockIdx.x;      // b*NQ + q
    int b = row >> 11;
    const int4* m4 = reinterpret_cast<const int4*>(mask + (size_t)row * NK);
    const float4* e4 = reinterpret_cast<const float4*>(g_e + b * NK);
    uint2* wh = reinterpret_cast<uint2*>(g_wh + (size_t)row * NK);

    int i0 = threadIdx.x, i1 = threadIdx.x + 256;   // NK/4 = 512 = 2*256
    int4 m0 = m4[i0], m1 = m4[i1];
    float4 e0 = e4[i0], e1 = e4[i1];

    float s = (m0.x ? e0.x : 0.f) + (m0.y ? e0.y : 0.f) +
              (m0.z ? e0.z : 0.f) + (m0.w ? e0.w : 0.f) +
              (m1.x ? e1.x : 0.f) + (m1.y ? e1.y : 0.f) +
              (m1.z ? e1.z : 0.f) + (m1.w ? e1.w : 0.f);
#pragma unroll
    for (int o = 16; o; o >>= 1) s += __shfl_xor_sync(0xffffffffu, s, o);
    __shared__ float sh[8];
    __shared__ float shi;
    if ((threadIdx.x & 31) == 0) sh[threadIdx.x >> 5] = s;
    __syncthreads();
    if (threadIdx.x == 0) {
        float t = 0.f;
#pragma unroll
        for (int i = 0; i < 8; i++) t += sh[i];
        shi = 1024.0f / t;
    }
    __syncthreads();
    float inv1024 = shi;

    float4 h0, h1;
    h0.x = m0.x ? e0.x * inv1024 : 0.f;
    h0.y = m0.y ? e0.y * inv1024 : 0.f;
    h0.z = m0.z ? e0.z * inv1024 : 0.f;
    h0.w = m0.w ? e0.w * inv1024 : 0.f;
    h1.x = m1.x ? e1.x * inv1024 : 0.f;
    h1.y = m1.y ? e1.y * inv1024 : 0.f;
    h1.z = m1.z ? e1.z * inv1024 : 0.f;
    h1.w = m1.w ? e1.w * inv1024 : 0.f;
    {
        __half2 lo = __floats2half2_rn(h0.x, h0.y), hi = __floats2half2_rn(h0.z, h0.w);
        uint2 u;
        u.x = *reinterpret_cast<uint32_t*>(&lo);
        u.y = *reinterpret_cast<uint32_t*>(&hi);
        wh[i0] = u;
        lo = __floats2half2_rn(h1.x, h1.y); hi = __floats2half2_rn(h1.z, h1.w);
        u.x = *reinterpret_cast<uint32_t*>(&lo);
        u.y = *reinterpret_cast<uint32_t*>(&hi);
        wh[i1] = u;
    }
}

// ---------------- kernel 3: context = (wh @ vh) * 2^-10  (fp16 mma.sync) -----
// CTA tile 128x128x64, 8 warps in 2(M) x 4(N), warp tile 64x32, 2 CTAs/SM.
// d0==0 CTAs additionally stream w = wh * 2^-10 (fp32) to global from the A
// stage already resident in smem (64MB of stores hidden under smem-bound work).
#define BM 128
#define BN 128
#define BK 64
#define NT (NK / BK)       // 32
#define ASTB 144           // bytes per A smem row (128 data + 16 pad)
#define BSTB 272           // bytes per B smem row (256 data + 16 pad)
#define ABYTES (BM * ASTB)                   // 18432
#define BBYTES (BK * BSTB)                   // 17408
#define STAGE_BYTES (ABYTES + BBYTES)        // 35840
#define STAGES 3
#define SMEM_GEMM (STAGES * STAGE_BYTES)     // 107520  (x2 CTAs = 210KB <= 228KB/SM)

__global__ void __launch_bounds__(256, 2)
k_gemm(float* __restrict__ ctx, float* __restrict__ wout) {
    extern __shared__ char smem[];
    uint32_t sb = smem_u32(smem);
    int tid = threadIdx.x, wid = tid >> 5, lane = tid & 31;
    int g = lane >> 2, t4 = lane & 3;
    int d0 = blockIdx.x * BN;
    int q0 = blockIdx.y * BM;
    int b = blockIdx.z;
    int wm = (wid >> 2) * 64;   // warp M offset in CTA tile
    int wn = (wid & 3) * 32;    // warp N offset in CTA tile

    const __half* Ag = g_wh + (size_t)(b * NQ + q0) * NK;     // [128 rows q][k] f16
    const __half* Bg = g_vh + (size_t)b * NK * ND + d0;       // [k][128 cols d] f16

    const uint32_t a_goff = (uint32_t)((tid >> 3) * NK + (tid & 7) * 8);
    const uint32_t a_soff = (uint32_t)((tid >> 3) * ASTB + (tid & 7) * 16);
    const uint32_t b_goff = (uint32_t)((tid >> 4) * ND + (tid & 15) * 8);
    const uint32_t b_soff = (uint32_t)((tid >> 4) * BSTB + (tid & 15) * 16);

    auto load_tile = [&](int t, int s) {
        uint32_t k0 = (uint32_t)t * BK;
        uint32_t As = sb + s * STAGE_BYTES;
        uint32_t Bs = As + ABYTES;
        const __half* ap = Ag + a_goff + k0;
        const __half* bp = Bg + (size_t)k0 * ND + b_goff;
#pragma unroll
        for (int j = 0; j < 4; j++)   // A: +32 rows per j
            cp16(As + a_soff + (uint32_t)j * (32 * ASTB), ap + (size_t)j * 32 * NK);
#pragma unroll
        for (int j = 0; j < 4; j++)   // B: +16 rows per j
            cp16(Bs + b_soff + (uint32_t)j * (16 * BSTB), bp + (size_t)j * 16 * ND);
        asm volatile("cp.async.commit_group;\n" ::: "memory");
    };

    float acc[4][4][4];
#pragma unroll
    for (int m = 0; m < 4; m++)
#pragma unroll
        for (int n = 0; n < 4; n++)
#pragma unroll
            for (int i = 0; i < 4; i++) acc[m][n][i] = 0.f;

    load_tile(0, 0);
    load_tile(1, 1);

    const uint32_t aldm0 = (uint32_t)(
        (wm + (lane & 7) + ((lane >> 3) & 1) * 8) * ASTB + (lane >> 4) * 16);
    const uint32_t bldm0 = (uint32_t)((lane & 15) * BSTB + (lane >> 4) * 16 + wn * 2);

    const float sc = 1.0f / 1024.0f;
    const bool emit_w = (blockIdx.x == 0);
    // w-store mapping: thread -> row tid>>1, k-half (tid&1)*32
    const uint32_t ws_soff = (uint32_t)((tid >> 1) * ASTB + (tid & 1) * 64);
    float* ws_dst = wout + (size_t)(b * NQ + q0 + (tid >> 1)) * NK + (tid & 1) * 32;

#pragma unroll 1
    for (int t = 0; t < NT; t++) {
        if (t + 2 < NT) asm volatile("cp.async.wait_group 1;\n" ::: "memory");
        else            asm volatile("cp.async.wait_group 0;\n" ::: "memory");
        __syncthreads();
        if (t + 2 < NT) load_tile(t + 2, (t + 2) % 3);

        uint32_t As = sb + (t % 3) * STAGE_BYTES;
        uint32_t Bs = As + ABYTES;

        if (emit_w) {   // stream fp32 weights from the A stage (read-only, race-free)
            uint32_t src = As + ws_soff;
            float4* dst = reinterpret_cast<float4*>(ws_dst + t * BK);
#pragma unroll
            for (int i = 0; i < 8; i++) {
                uint32_t u0 = lds_u32(src + i * 8);
                uint32_t u1 = lds_u32(src + i * 8 + 4);
                float2 f0 = __half22float2(*reinterpret_cast<__half2*>(&u0));
                float2 f1 = __half22float2(*reinterpret_cast<__half2*>(&u1));
                dst[i] = make_float4(f0.x * sc, f0.y * sc, f1.x * sc, f1.y * sc);
            }
        }

#pragma unroll
        for (int c = 0; c < 4; c++) {    // 4 chunks of K=16
            uint32_t a[4][4], bb[4][2];
#pragma unroll
            for (int m = 0; m < 4; m++)
                ldsm4(a[m][0], a[m][1], a[m][2], a[m][3],
                      As + aldm0 + (uint32_t)(m * 16 * ASTB + c * 32));
            ldsm4t(bb[0][0], bb[0][1], bb[1][0], bb[1][1],
                   Bs + bldm0 + (uint32_t)(c * 16 * BSTB));
            ldsm4t(bb[2][0], bb[2][1], bb[3][0], bb[3][1],
                   Bs + bldm0 + (uint32_t)(c * 16 * BSTB + 32));
#pragma unroll
            for (int m = 0; m < 4; m++)
#pragma unroll
                for (int n = 0; n < 4; n++) {
                    asm volatile(
                        "mma.sync.aligned.m16n8k16.row.col.f32.f16.f16.f32 "
                        "{%0,%1,%2,%3}, {%4,%5,%6,%7}, {%8,%9}, {%0,%1,%2,%3};"
                        : "+f"(acc[m][n][0]), "+f"(acc[m][n][1]),
                          "+f"(acc[m][n][2]), "+f"(acc[m][n][3])
                        : "r"(a[m][0]), "r"(a[m][1]), "r"(a[m][2]), "r"(a[m][3]),
                          "r"(bb[n][0]), "r"(bb[n][1]));
                }
        }
    }

    // epilogue: undo the 1024x A scaling (exact power of two).
#pragma unroll
    for (int m = 0; m < 4; m++) {
        int row = q0 + wm + m * 16 + g;
#pragma unroll
        for (int n = 0; n < 4; n++) {
            int col = d0 + wn + n * 8 + 2 * t4;
            float* p0 = ctx + (size_t)(b * NQ + row) * ND + col;
            float* p1 = ctx + (size_t)(b * NQ + row + 8) * ND + col;
            *reinterpret_cast<float2*>(p0) = make_float2(acc[m][n][0] * sc, acc[m][n][1] * sc);
            *reinterpret_cast<float2*>(p1) = make_float2(acc[m][n][2] * sc, acc[m][n][3] * sc);
        }
    }
}

// ---------------- launcher ----------------
extern "C" void kernel_launch(void* const* d_in, const int* in_sizes, int n_in,
                              void* d_out, int out_size) {
    // inputs: [0]=query (UNUSED: q_sum cancels in softmax), [1]=value, [2]=attention_mask
    const float* value = (const float*)d_in[1];
    const int* mask = (const int*)d_in[2];

    const size_t CTXN = (size_t)NB * NQ * ND;   // 8,388,608
    const size_t WN   = (size_t)NB * NQ * NK;   // 16,777,216

    float* ctx;
    float* w;
    void* scr_w = nullptr;
    void* scr_ctx = nullptr;
    cudaGetSymbolAddress(&scr_w, g_w);
    cudaGetSymbolAddress(&scr_ctx, g_ctx);

    if ((size_t)out_size >= CTXN + WN) {
        ctx = (float*)d_out;
        w = (float*)d_out + CTXN;
    } else if ((size_t)out_size == WN) {
        w = (float*)d_out;
        ctx = (float*)scr_ctx;
    } else {
        ctx = (float*)d_out;
        w = (float*)scr_w;
    }

    cudaFuncSetAttribute(k_gemm, cudaFuncAttributeMaxDynamicSharedMemorySize, SMEM_GEMM);

    k_rowexp<<<NB * NK / 8, 256>>>(value);
    k_weights<<<NB * NQ, 256>>>(mask);
    k_gemm<<<dim3(ND / BN, NQ / BM, NB), 256, SMEM_GEMM>>>(ctx, w);
}